// round 16
// baseline (speedup 1.0000x reference)
#include <cuda_runtime.h>

// SpatialGRU wavefront v12: v11 core + warp-level operand dedup.
// Warp = 8 col-subs x 4 rowgroups (thread = 4r x 4c). W: one 128B line per
// warp per k. A: transposed H tiles [k][row] -> one 64B LDS per warp per k.
// Row-major H copies kept for epilogue/GEMM2 (dual storage).

namespace cfg {
constexpr int TP = 36;            // transposed-tile row pitch (32 rows + pad)
constexpr int SM_HTt = 0;         // 64 x 36
constexpr int SM_P0t = 2304;
constexpr int SM_P1t = 4608;
constexpr int SM_HTr = 6912;      // 32 x 64
constexpr int SM_P0r = 8960;
constexpr int SM_P1r = 11008;
constexpr int SM_RR  = 13056;     // 32 x 192
constexpr int SM_Z   = 19200;     // 32 x 256
constexpr int SM_W2  = 27392;     // 192 x 64
constexpr int SM_FLOATS = 39680;
constexpr int SM_BYTES = SM_FLOATS * 4;   // 158720
}

__device__ __align__(16) float g_s[(size_t)4096 * 64 * 512];   // [cell][b][512]
__device__ __align__(16) float g_h[(size_t)4096 * 64 * 64];    // [cell][b][u]
__device__ __align__(16) float g_wtrz[192 * 448];              // [k][n]
__device__ __align__(16) float g_wt2[192 * 64];                // [k][n] (U_w^T)
__device__ __align__(16) float g_wx[16 * 512];                 // [c][n]
__device__ __align__(16) float g_bias[512];
__device__ int g_flag[128];                                    // [half*64 + r]

// ---------------- helpers ----------------------------------------------------
__device__ __forceinline__ unsigned long long f2_pack(float lo, float hi) {
    unsigned long long d;
    asm("mov.b64 %0, {%1, %2};" : "=l"(d) : "f"(lo), "f"(hi));
    return d;
}
__device__ __forceinline__ unsigned long long f2_dup(float a) {
    unsigned long long d;
    asm("mov.b64 %0, {%1, %1};" : "=l"(d) : "f"(a));
    return d;
}
__device__ __forceinline__ float2 f2_unpack(unsigned long long v) {
    float2 r;
    asm("mov.b64 {%0, %1}, %2;" : "=f"(r.x), "=f"(r.y) : "l"(v));
    return r;
}
__device__ __forceinline__ unsigned long long f2_fma(unsigned long long a,
                                                     unsigned long long b,
                                                     unsigned long long c) {
    unsigned long long d;
    asm("fma.rn.f32x2 %0, %1, %2, %3;" : "=l"(d) : "l"(a), "l"(b), "l"(c));
    return d;
}
__device__ __forceinline__ unsigned long long f2_add(unsigned long long a,
                                                     unsigned long long b) {
    unsigned long long d;
    asm("add.rn.f32x2 %0, %1, %2;" : "=l"(d) : "l"(a), "l"(b));
    return d;
}
__device__ __forceinline__ int ld_acq(const int* p) {
    int v;
    asm volatile("ld.global.acquire.gpu.b32 %0, [%1];" : "=r"(v) : "l"(p) : "memory");
    return v;
}
__device__ __forceinline__ void st_rel(int* p, int v) {
    asm volatile("st.global.release.gpu.b32 [%0], %1;" :: "l"(p), "r"(v) : "memory");
}
__device__ __forceinline__ float fsigmoid(float x) { return 1.f / (1.f + __expf(-x)); }

// ---------------- setup ------------------------------------------------------
__global__ void k_nop() {}

__global__ void k_prep(const float* __restrict__ wr_w, const float* __restrict__ wz_w,
                       const float* __restrict__ wij_w, const float* __restrict__ U_w,
                       const float* __restrict__ wr_b, const float* __restrict__ wz_b,
                       const float* __restrict__ wij_b) {
    int idx = blockIdx.x * 256 + threadIdx.x;   // 418*256 = 107008 exact
    const int T1 = 192 * 448, T2 = T1 + 192 * 64, T3 = T2 + 16 * 512;
    if (idx < T1) {
        int k = idx / 448, n = idx % 448;
        g_wtrz[idx] = (n < 192) ? wr_w[n * 208 + k] : wz_w[(n - 192) * 208 + k];
    } else if (idx < T2) {
        int i2 = idx - T1;
        int k = i2 / 64, n = i2 % 64;
        g_wt2[i2] = U_w[n * 192 + k];
    } else if (idx < T3) {
        int i2 = idx - T2;
        int c = i2 / 512, n = i2 % 512;
        g_wx[i2] = (n < 192)   ? wr_w[n * 208 + 192 + c]
                 : (n < 448) ? wz_w[(n - 192) * 208 + 192 + c]
                             : wij_w[(n - 448) * 16 + c];
    } else {
        int n = idx - T3;
        g_bias[n] = (n < 192) ? wr_b[n] : (n < 448) ? wz_b[n - 192] : wij_b[n - 448];
    }
    if (idx < 128) g_flag[idx] = 0;
}

// g_s[cell][row][col] = sum_c x[row][c] * Wx[c][col] + bias[col]
__global__ __launch_bounds__(256) void k_sxz(const float* __restrict__ inputs) {
    __shared__ float sW[16 * 512];
    __shared__ float sb[512];
    __shared__ float sx[64 * 16];
    const int cell = blockIdx.x;
    const int tid = threadIdx.x;
    for (int i = tid; i < 8192; i += 256) sW[i] = g_wx[i];
    for (int i = tid; i < 512; i += 256) sb[i] = g_bias[i];
    for (int i = tid; i < 1024; i += 256) sx[i] = inputs[(size_t)i * 4096 + cell];
    __syncthreads();
    const int ryq = tid >> 4, cx = tid & 15;
    const int row0 = ryq * 4;
    float* outp = g_s + (size_t)cell * 64 * 512;
#pragma unroll 1
    for (int p = 0; p < 4; ++p) {
        const int col0 = p * 128 + cx * 8;
        unsigned long long acc[4][4];
        {
            float4 b0 = *reinterpret_cast<const float4*>(&sb[col0]);
            float4 b1 = *reinterpret_cast<const float4*>(&sb[col0 + 4]);
            unsigned long long p0 = f2_pack(b0.x, b0.y), p1 = f2_pack(b0.z, b0.w);
            unsigned long long p2 = f2_pack(b1.x, b1.y), p3 = f2_pack(b1.z, b1.w);
#pragma unroll
            for (int i = 0; i < 4; ++i) {
                acc[i][0] = p0; acc[i][1] = p1; acc[i][2] = p2; acc[i][3] = p3;
            }
        }
#pragma unroll
        for (int k = 0; k < 16; k += 4) {
            float4 a[4];
#pragma unroll
            for (int i = 0; i < 4; ++i)
                a[i] = *reinterpret_cast<const float4*>(&sx[(row0 + i) * 16 + k]);
#pragma unroll
            for (int kk = 0; kk < 4; ++kk) {
                ulonglong2 w0 = *reinterpret_cast<const ulonglong2*>(sW + (k + kk) * 512 + col0);
                ulonglong2 w1 = *reinterpret_cast<const ulonglong2*>(sW + (k + kk) * 512 + col0 + 4);
#pragma unroll
                for (int i = 0; i < 4; ++i) {
                    unsigned long long d = f2_dup(reinterpret_cast<const float*>(&a[i])[kk]);
                    acc[i][0] = f2_fma(d, w0.x, acc[i][0]);
                    acc[i][1] = f2_fma(d, w0.y, acc[i][1]);
                    acc[i][2] = f2_fma(d, w1.x, acc[i][2]);
                    acc[i][3] = f2_fma(d, w1.y, acc[i][3]);
                }
            }
        }
#pragma unroll
        for (int i = 0; i < 4; ++i) {
            float2 u0 = f2_unpack(acc[i][0]), u1 = f2_unpack(acc[i][1]);
            float2 u2 = f2_unpack(acc[i][2]), u3 = f2_unpack(acc[i][3]);
            float4 o0 = {u0.x, u0.y, u1.x, u1.y};
            float4 o1 = {u2.x, u2.y, u3.x, u3.y};
            *reinterpret_cast<float4*>(&outp[(row0 + i) * 512 + col0]) = o0;
            *reinterpret_cast<float4*>(&outp[(row0 + i) * 512 + col0 + 4]) = o1;
        }
    }
}

// ---- GEMM1 K=64 segment: A transposed [k][36], thread = 4 rows x 4 cols ----
__device__ __forceinline__ void gemm1_seg(const float* __restrict__ At, int row0,
                                          const float* __restrict__ Wc,
                                          unsigned long long acc[4][2]) {
#pragma unroll 4
    for (int k = 0; k < 64; k += 4) {
        float4 a[4];
        ulonglong2 w[4];
#pragma unroll
        for (int kk = 0; kk < 4; ++kk) {
            a[kk] = *reinterpret_cast<const float4*>(&At[(k + kk) * cfg::TP + row0]);
            w[kk] = *reinterpret_cast<const ulonglong2*>(Wc + (k + kk) * 448);
        }
#pragma unroll
        for (int kk = 0; kk < 4; ++kk) {
#pragma unroll
            for (int i = 0; i < 4; ++i) {
                unsigned long long d =
                    f2_dup(reinterpret_cast<const float*>(&a[kk])[i]);
                acc[i][0] = f2_fma(d, w[kk].x, acc[i][0]);
                acc[i][1] = f2_fma(d, w[kk].y, acc[i][1]);
            }
        }
    }
}

// ---------------- wavefront kernel -------------------------------------------
__global__ __launch_bounds__(896, 1) void k_wave(float* __restrict__ out) {
    extern __shared__ float sm[];
    float* sHTt = sm + cfg::SM_HTt;
    float* sHTr = sm + cfg::SM_HTr;
    float* sRR  = sm + cfg::SM_RR;
    float* sZ   = sm + cfg::SM_Z;
    float* sW2  = sm + cfg::SM_W2;

    const int tid = threadIdx.x;
    const int bid = blockIdx.x;
    const int r = bid & 63, half = bid >> 6;
    const int rb0 = half * 32;                  // batch-row base
    const int wid = tid >> 5, lane = tid & 31;
    const int cgw = wid % 14, rh = wid / 14;    // 14 col-warps x 2 row-halves
    const int cq = lane & 7, rq = lane >> 3;
    const int col0 = cgw * 32 + cq * 4;         // 4 cols/thread
    const int row0 = rh * 16 + rq * 4;          // 4 rows/thread
    const int blk = col0 >> 6, off = col0 & 63;
    const int tx2 = tid & 15, ty2 = tid >> 4;   // GEMM2 (tid < 256)
    const int lc0 = 4 * tx2;

    for (int i = tid; i < 13056; i += 896) sm[i] = 0.f;   // all 6 H tiles = 0
    for (int i = tid; i < 3072; i += 896)                 // stage U_w^T once
        reinterpret_cast<float4*>(sW2)[i] =
            reinterpret_cast<const float4*>(g_wt2)[i];
    __syncthreads();

#pragma unroll 1
    for (int l = 0; l < 64; ++l) {
        float* sHLt = sm + ((l & 1) ? cfg::SM_P1t : cfg::SM_P0t);
        float* sHDt = sm + ((l & 1) ? cfg::SM_P0t : cfg::SM_P1t);
        float* sHLr = sm + ((l & 1) ? cfg::SM_P1r : cfg::SM_P0r);
        float* sHDr = sm + ((l & 1) ? cfg::SM_P0r : cfg::SM_P1r);

        const size_t cellbase = (size_t)(l * 64 + r) * 64 * 512;

        // issue g_s loads first; consumed only after the pre-segments
        float4 sv[4];
        {
            const float* sp = g_s + cellbase + (size_t)(rb0 + row0) * 512 + col0;
#pragma unroll
            for (int i = 0; i < 4; ++i)
                sv[i] = *reinterpret_cast<const float4*>(sp + i * 512);
        }
        float4 sv2a, sv2b;
        if (tid < 256) {
            sv2a = *reinterpret_cast<const float4*>(
                g_s + cellbase + (size_t)(rb0 + ty2) * 512 + 448 + lc0);
            sv2b = *reinterpret_cast<const float4*>(
                g_s + cellbase + (size_t)(rb0 + ty2 + 16) * 512 + 448 + lc0);
        }

        // ---- PRE (independent of h_left): HT + HD segments of GEMM1 ----
        unsigned long long acc[4][2];
#pragma unroll
        for (int i = 0; i < 4; ++i) { acc[i][0] = 0ull; acc[i][1] = 0ull; }
        gemm1_seg(sHTt, row0, g_wtrz + col0, acc);                // h_top
        gemm1_seg(sHDt, row0, g_wtrz + 128 * 448 + col0, acc);    // h_diag
#pragma unroll
        for (int i = 0; i < 4; ++i) {                             // += s (x-proj)
            acc[i][0] = f2_add(acc[i][0], f2_pack(sv[i].x, sv[i].y));
            acc[i][1] = f2_add(acc[i][1], f2_pack(sv[i].z, sv[i].w));
        }

        // ---- wait for left neighbor, then load h_left (both layouts) ----
        if (r > 0) {
            if (tid == 0) {
                while (ld_acq(&g_flag[half * 64 + r - 1]) < l + 1) __nanosleep(32);
            }
            __syncthreads();
            if (tid < 512) {
                int row = tid >> 4, kq = tid & 15;
                float4 v = *reinterpret_cast<const float4*>(
                    g_h + (size_t)(l * 64 + (r - 1)) * 4096 +
                    (size_t)(rb0 + row) * 64 + kq * 4);
                *reinterpret_cast<float4*>(&sHLr[row * 64 + kq * 4]) = v;
                sHLt[(kq * 4 + 0) * cfg::TP + row] = v.x;
                sHLt[(kq * 4 + 1) * cfg::TP + row] = v.y;
                sHLt[(kq * 4 + 2) * cfg::TP + row] = v.z;
                sHLt[(kq * 4 + 3) * cfg::TP + row] = v.w;
            }
            __syncthreads();
        }

        // ---- POST: h_left segment of GEMM1 + epilogue ----
        gemm1_seg(sHLt, row0, g_wtrz + 64 * 448 + col0, acc);     // h_left

        if (blk < 3) {
            const float* HU = (blk == 0) ? sHLr : (blk == 1) ? sHTr : sHDr;
#pragma unroll
            for (int i = 0; i < 4; ++i) {
                int row = row0 + i;
                float2 u0 = f2_unpack(acc[i][0]), u1 = f2_unpack(acc[i][1]);
                float4 hu = *reinterpret_cast<const float4*>(&HU[row * 64 + off]);
                float4 o = {hu.x * fsigmoid(u0.x), hu.y * fsigmoid(u0.y),
                            hu.z * fsigmoid(u1.x), hu.w * fsigmoid(u1.y)};
                *reinterpret_cast<float4*>(&sRR[row * 192 + blk * 64 + off]) = o;
            }
        } else {
#pragma unroll
            for (int i = 0; i < 4; ++i) {
                int row = row0 + i;
                float2 u0 = f2_unpack(acc[i][0]), u1 = f2_unpack(acc[i][1]);
                float4 o = {u0.x, u0.y, u1.x, u1.y};
                *reinterpret_cast<float4*>(&sZ[row * 256 + (blk - 3) * 64 + off]) = o;
            }
        }
        __syncthreads();

        // ---- GEMM2 (tid < 256): rr*hu @ U_w^T + s[:,448:], gates, h ----
        if (tid < 256) {
            unsigned long long acc0[2], acc1[2];
            acc0[0] = f2_pack(sv2a.x, sv2a.y);
            acc1[0] = f2_pack(sv2a.z, sv2a.w);
            acc0[1] = f2_pack(sv2b.x, sv2b.y);
            acc1[1] = f2_pack(sv2b.z, sv2b.w);
            const float* A0 = sRR + ty2 * 192;
            const float* A1 = sRR + (ty2 + 16) * 192;
            const float* Wc = sW2 + lc0;
#pragma unroll 4
            for (int k = 0; k < 192; k += 4) {
                float4 a0 = *reinterpret_cast<const float4*>(&A0[k]);
                float4 a1 = *reinterpret_cast<const float4*>(&A1[k]);
#pragma unroll
                for (int kk = 0; kk < 4; ++kk) {
                    ulonglong2 w = *reinterpret_cast<const ulonglong2*>(
                        Wc + (k + kk) * 64);
                    unsigned long long d0 =
                        f2_dup(reinterpret_cast<const float*>(&a0)[kk]);
                    unsigned long long d1 =
                        f2_dup(reinterpret_cast<const float*>(&a1)[kk]);
                    acc0[0] = f2_fma(d0, w.x, acc0[0]);
                    acc1[0] = f2_fma(d0, w.y, acc1[0]);
                    acc0[1] = f2_fma(d1, w.x, acc0[1]);
                    acc1[1] = f2_fma(d1, w.y, acc1[1]);
                }
            }

#pragma unroll
            for (int i = 0; i < 2; ++i) {
                int row = ty2 + 16 * i;
                float2 v01 = f2_unpack(acc0[i]), v23 = f2_unpack(acc1[i]);
                float hn[4] = {tanhf(v01.x), tanhf(v01.y), tanhf(v23.x), tanhf(v23.y)};
                const float* zr = sZ + row * 256 + lc0;
                float4 zi4 = *reinterpret_cast<const float4*>(zr);
                float4 zl4 = *reinterpret_cast<const float4*>(zr + 64);
                float4 zt4 = *reinterpret_cast<const float4*>(zr + 128);
                float4 zd4 = *reinterpret_cast<const float4*>(zr + 192);
                float4 hl4 = *reinterpret_cast<const float4*>(&sHLr[row * 64 + lc0]);
                float4 ht4 = *reinterpret_cast<const float4*>(&sHTr[row * 64 + lc0]);
                float4 hd4 = *reinterpret_cast<const float4*>(&sHDr[row * 64 + lc0]);
                float zi[4] = {zi4.x, zi4.y, zi4.z, zi4.w};
                float zl[4] = {zl4.x, zl4.y, zl4.z, zl4.w};
                float zt[4] = {zt4.x, zt4.y, zt4.z, zt4.w};
                float zd[4] = {zd4.x, zd4.y, zd4.z, zd4.w};
                float hl[4] = {hl4.x, hl4.y, hl4.z, hl4.w};
                float ht[4] = {ht4.x, ht4.y, ht4.z, ht4.w};
                float hd[4] = {hd4.x, hd4.y, hd4.z, hd4.w};
                float h[4];
#pragma unroll
                for (int j = 0; j < 4; ++j) {
                    float m = fmaxf(fmaxf(zi[j], zl[j]), fmaxf(zt[j], zd[j]));
                    float ei = __expf(zi[j] - m), el = __expf(zl[j] - m);
                    float et = __expf(zt[j] - m), ed = __expf(zd[j] - m);
                    float inv = 1.f / (ei + el + et + ed);
                    h[j] = (el * hl[j] + et * ht[j] + ed * hd[j] + ei * hn[j]) * inv;
                }
                float4 h4 = {h[0], h[1], h[2], h[3]};
                *reinterpret_cast<float4*>(&sHTr[row * 64 + lc0]) = h4;
                sHTt[(lc0 + 0) * cfg::TP + row] = h4.x;
                sHTt[(lc0 + 1) * cfg::TP + row] = h4.y;
                sHTt[(lc0 + 2) * cfg::TP + row] = h4.z;
                sHTt[(lc0 + 3) * cfg::TP + row] = h4.w;
                if (r < 63)
                    *reinterpret_cast<float4*>(
                        g_h + ((size_t)(l * 64 + r) * 64 + rb0 + row) * 64 + lc0) = h4;
                if (l == 63 && r == 63)
                    *reinterpret_cast<float4*>(out + (rb0 + row) * 64 + lc0) = h4;
            }
        }
        __syncthreads();   // orders all stores before the release below
        if (tid == 0) st_rel(&g_flag[half * 64 + r], l + 1);
    }
}

// ---------------- launch ------------------------------------------------------
extern "C" void kernel_launch(void* const* d_in, const int* in_sizes, int n_in,
                              void* d_out, int out_size) {
    const float* inputs = (const float*)d_in[0];
    const float* wr_w = (const float*)d_in[1];
    const float* wr_b = (const float*)d_in[2];
    const float* wz_w = (const float*)d_in[3];
    const float* wz_b = (const float*)d_in[4];
    const float* wij_w = (const float*)d_in[5];
    const float* wij_b = (const float*)d_in[6];
    const float* U_w = (const float*)d_in[7];
    float* out = (float*)d_out;

    cudaFuncSetAttribute(k_wave, cudaFuncAttributeMaxDynamicSharedMemorySize,
                         cfg::SM_BYTES);

    k_nop<<<1, 1>>>();
    k_prep<<<418, 256>>>(wr_w, wz_w, wij_w, U_w, wr_b, wz_b, wij_b);
    k_sxz<<<4096, 256>>>(inputs);
    k_wave<<<128, 896, cfg::SM_BYTES>>>(out);
}